// round 1
// baseline (speedup 1.0000x reference)
#include <cuda_runtime.h>
#include <math.h>

// Problem constants
#define NN 768
#define DD 64
#define SS 32
#define PP 4

// RBF constants: mu = linspace(0,12,32) -> step 12/31 ; sigma = 12/32
#define RBF_STEP   (12.0f / 31.0f)
#define NEG_INV2S2 (-3.5555555555555554f)   // -1/(2*sigma^2), sigma=0.375

// Scratch (no cudaMalloc allowed): A = hid @ W_rbf  -> [x][j][s], 6 MB
__device__ float g_A[NN * DD * SS];
__device__ float g_partial[NN * PP];

// ---------------------------------------------------------------------------
// Kernel 1: A[x, j*32+s] = sum_i hid[x,i] * W[i*2048 + j*32 + s]
// GEMM M=768, N=2048, K=64. Tile 128x128, K chunks of 32. 256 thr, 8x8 micro.
// ---------------------------------------------------------------------------
__global__ __launch_bounds__(256)
void prep_kernel(const float* __restrict__ hid, const float* __restrict__ W) {
    __shared__ float sHk[32][129];   // [k][m]
    __shared__ float sW[32][128];    // [k][n]

    const int tid = threadIdx.x;
    const int tx = tid & 15;         // 0..15 -> n micro
    const int ty = tid >> 4;         // 0..15 -> m micro
    const int m0 = blockIdx.y * 128;
    const int n0 = blockIdx.x * 128;

    float acc[8][8];
#pragma unroll
    for (int i = 0; i < 8; ++i)
#pragma unroll
        for (int j = 0; j < 8; ++j) acc[i][j] = 0.0f;

    for (int kt = 0; kt < 64; kt += 32) {
        __syncthreads();
        // hid tile: hid[m0+m][kt+k] -> sHk[k][m]   (128 m x 32 k)
        {
            const int m  = tid >> 3;        // 0..31
            const int k4 = (tid & 7) * 4;   // 0..28
#pragma unroll
            for (int r = 0; r < 4; ++r) {
                const int mm = m + r * 32;
                float4 v = *(const float4*)(hid + (m0 + mm) * DD + kt + k4);
                sHk[k4 + 0][mm] = v.x;
                sHk[k4 + 1][mm] = v.y;
                sHk[k4 + 2][mm] = v.z;
                sHk[k4 + 3][mm] = v.w;
            }
        }
        // W tile: W[(kt+r)][n0+c]  (32 k x 128 n), row stride 2048
        {
            const int r  = tid >> 5;        // 0..7
            const int c4 = (tid & 31) * 4;  // 0..124
#pragma unroll
            for (int q = 0; q < 4; ++q) {
                *(float4*)(&sW[r + q * 8][c4]) =
                    *(const float4*)(W + (size_t)(kt + r + q * 8) * 2048 + n0 + c4);
            }
        }
        __syncthreads();

#pragma unroll 8
        for (int k = 0; k < 32; ++k) {
            float a[8], b[8];
#pragma unroll
            for (int q = 0; q < 8; ++q) a[q] = sHk[k][ty * 8 + q];
            float4 b0 = *(const float4*)(&sW[k][tx * 8]);
            float4 b1 = *(const float4*)(&sW[k][tx * 8 + 4]);
            b[0] = b0.x; b[1] = b0.y; b[2] = b0.z; b[3] = b0.w;
            b[4] = b1.x; b[5] = b1.y; b[6] = b1.z; b[7] = b1.w;
#pragma unroll
            for (int i = 0; i < 8; ++i)
#pragma unroll
                for (int j = 0; j < 8; ++j) acc[i][j] += a[i] * b[j];
        }
    }

#pragma unroll
    for (int i = 0; i < 8; ++i) {
        const int m = m0 + ty * 8 + i;
        float4 v0 = make_float4(acc[i][0], acc[i][1], acc[i][2], acc[i][3]);
        float4 v1 = make_float4(acc[i][4], acc[i][5], acc[i][6], acc[i][7]);
        *(float4*)(g_A + (size_t)m * 2048 + n0 + tx * 8)     = v0;
        *(float4*)(g_A + (size_t)m * 2048 + n0 + tx * 8 + 4) = v1;
    }
}

// ---------------------------------------------------------------------------
// Kernel 2: for each x (block), stream y in tiles of 128.
// 256 threads: tid&127 -> y in tile, tid>>7 -> which half of s (16 each).
// inter[s] = b[s] + sum_j A[x][j][s] * hid[y][j]  (A broadcast from smem)
// then per pose p: d = |c_x - c_y|, acc_p += sum_s inter[s]*exp(-(d-mu_s)^2/2s^2)
// Deterministic block reduction -> g_partial[x][p].
// ---------------------------------------------------------------------------
__global__ __launch_bounds__(256, 2)
void main_kernel(const float* __restrict__ hid, const float* __restrict__ coords,
                 const float* __restrict__ b_rbf) {
    __shared__ float sA[DD * SS];        // 8 KB  [j][s]
    __shared__ float sH[DD][129];        // 33 KB [j][y]
    __shared__ float sCy[PP][3][128];    // 6 KB
    __shared__ float sb[SS];
    __shared__ float scx[PP * 3];
    __shared__ float sred[8][4];

    const int x   = blockIdx.x;
    const int tid = threadIdx.x;
    const int y_l = tid & 127;
    const int sh  = tid >> 7;            // 0 or 1
    const int s_base = sh * 16;

    // Load A_x (2048 floats, coalesced float4)
    {
        const float4* gA4 = (const float4*)(g_A + (size_t)x * (DD * SS));
        float4* sA4w = (float4*)sA;
        sA4w[tid]       = gA4[tid];
        sA4w[tid + 256] = gA4[tid + 256];
    }
    if (tid < SS) sb[tid] = b_rbf[tid];
    if (tid < PP * 3) {
        const int p = tid / 3, c = tid - p * 3;
        scx[tid] = coords[(size_t)(p * NN + x) * 3 + c];
    }

    float acc[PP] = {0.f, 0.f, 0.f, 0.f};

    for (int ytile = 0; ytile < NN; ytile += 128) {
        __syncthreads();   // previous epilogue done before overwriting tiles
        // hid tile transposed: hid[ytile+y][j] -> sH[j][y]
        {
            const int yy = tid >> 4;          // 0..15
            const int j4 = (tid & 15) * 4;    // 0..60
#pragma unroll
            for (int r = 0; r < 8; ++r) {
                const int y = yy + r * 16;
                float4 v = *(const float4*)(hid + (size_t)(ytile + y) * DD + j4);
                sH[j4 + 0][y] = v.x;
                sH[j4 + 1][y] = v.y;
                sH[j4 + 2][y] = v.z;
                sH[j4 + 3][y] = v.w;
            }
        }
        // coords tile: coords[p][ytile+y][c] -> sCy[p][c][y]
        for (int idx = tid; idx < PP * 128 * 3; idx += 256) {
            const int p   = idx / (128 * 3);
            const int rem = idx - p * (128 * 3);
            const int y   = rem / 3;
            const int c   = rem - y * 3;
            sCy[p][c][y] = coords[(size_t)(p * NN + ytile + y) * 3 + c];
        }
        __syncthreads();

        // inter for (x, ytile+y_l), 16 s values owned by this thread
        float inter[16];
#pragma unroll
        for (int s = 0; s < 16; ++s) inter[s] = sb[s_base + s];

        const float4* sA4 = (const float4*)sA;
        const int abase = sh * 4;
#pragma unroll 4
        for (int j = 0; j < DD; ++j) {
            const float h = sH[j][y_l];
            float4 a0 = sA4[j * 8 + abase + 0];
            float4 a1 = sA4[j * 8 + abase + 1];
            float4 a2 = sA4[j * 8 + abase + 2];
            float4 a3 = sA4[j * 8 + abase + 3];
            inter[0]  += a0.x * h; inter[1]  += a0.y * h;
            inter[2]  += a0.z * h; inter[3]  += a0.w * h;
            inter[4]  += a1.x * h; inter[5]  += a1.y * h;
            inter[6]  += a1.z * h; inter[7]  += a1.w * h;
            inter[8]  += a2.x * h; inter[9]  += a2.y * h;
            inter[10] += a2.z * h; inter[11] += a2.w * h;
            inter[12] += a3.x * h; inter[13] += a3.y * h;
            inter[14] += a3.z * h; inter[15] += a3.w * h;
        }

        const int yg = ytile + y_l;
        if (yg != x) {
            const float mu_base = (float)s_base * RBF_STEP;
#pragma unroll
            for (int p = 0; p < PP; ++p) {
                const float dx = scx[p * 3 + 0] - sCy[p][0][y_l];
                const float dy = scx[p * 3 + 1] - sCy[p][1][y_l];
                const float dz = scx[p * 3 + 2] - sCy[p][2][y_l];
                const float d  = sqrtf(dx * dx + dy * dy + dz * dz + 1e-12f);
                float t = d - mu_base;
                float a = 0.0f;
#pragma unroll
                for (int s = 0; s < 16; ++s) {
                    const float e = __expf(t * t * NEG_INV2S2);
                    a += inter[s] * e;
                    t -= RBF_STEP;
                }
                acc[p] += a;
            }
        }
    }

    // Deterministic block reduction: warp shuffle, then smem across 8 warps
#pragma unroll
    for (int p = 0; p < PP; ++p) {
#pragma unroll
        for (int off = 16; off > 0; off >>= 1)
            acc[p] += __shfl_down_sync(0xffffffffu, acc[p], off);
    }
    const int wid = tid >> 5, lane = tid & 31;
    if (lane == 0) {
#pragma unroll
        for (int p = 0; p < PP; ++p) sred[wid][p] = acc[p];
    }
    __syncthreads();
    if (tid < PP) {
        float s = 0.0f;
#pragma unroll
        for (int w = 0; w < 8; ++w) s += sred[w][tid];
        g_partial[x * PP + tid] = s;
    }
}

// ---------------------------------------------------------------------------
// Kernel 3: reduce 768 partials per pose, scale, add bias.
// ---------------------------------------------------------------------------
__global__ __launch_bounds__(256)
void finalize_kernel(const float* __restrict__ weight, const float* __restrict__ bias,
                     float* __restrict__ out) {
    __shared__ float red[256][4];
    const int tid = threadIdx.x;
    float a[PP] = {0.f, 0.f, 0.f, 0.f};
    for (int i = tid; i < NN; i += 256) {
#pragma unroll
        for (int p = 0; p < PP; ++p) a[p] += g_partial[i * PP + p];
    }
#pragma unroll
    for (int p = 0; p < PP; ++p) red[tid][p] = a[p];
    for (int off = 128; off > 0; off >>= 1) {
        __syncthreads();
        if (tid < off) {
#pragma unroll
            for (int p = 0; p < PP; ++p) red[tid][p] += red[tid + off][p];
        }
    }
    __syncthreads();
    if (tid < PP) {
        const float scale = 1.0f / (float)((size_t)NN * NN * SS);  // ENERGY_SCALE = 1
        out[tid] = red[0][tid] * scale * weight[0] + bias[0];
    }
}

// ---------------------------------------------------------------------------
extern "C" void kernel_launch(void* const* d_in, const int* in_sizes, int n_in,
                              void* d_out, int out_size) {
    const float* hid    = (const float*)d_in[0];   // [768,64]
    const float* coords = (const float*)d_in[1];   // [4,768,3]
    const float* W_rbf  = (const float*)d_in[2];   // [64,64,32]
    const float* b_rbf  = (const float*)d_in[3];   // [32]
    const float* weight = (const float*)d_in[4];   // [1]
    const float* bias   = (const float*)d_in[5];   // [1]
    float* out = (float*)d_out;                    // [4]

    prep_kernel<<<dim3(16, 6), 256>>>(hid, W_rbf);
    main_kernel<<<NN, 256>>>(hid, coords, b_rbf);
    finalize_kernel<<<1, 256>>>(weight, bias, out);
}

// round 3
// speedup vs baseline: 1.7575x; 1.7575x over previous
#include <cuda_runtime.h>
#include <math.h>

// Problem constants
#define NN 768
#define DD 64
#define SS 32
#define PP 4

// RBF constants: mu = linspace(0,12,32) -> step 12/31 ; sigma = 12/32
#define RBF_STEP    (12.0f / 31.0f)
// exp(-t^2/(2*sigma^2)) = 2^(C2LOG * t^2), C2LOG = -1/(2*sigma^2) * log2(e)
#define C2LOG       (-5.1295823676f)

// Scratch: Asym = hid @ (W + W^T_ij)  -> [x][j][s], 6 MB
__device__ float g_A[NN * DD * SS];
__device__ float g_partial[NN * PP];

__device__ __forceinline__ float ex2f(float x) {
    float r;
    asm("ex2.approx.f32 %0, %1;" : "=f"(r) : "f"(x));
    return r;
}

// ---------------------------------------------------------------------------
// Kernel 1: Asym[x, j*32+s] = sum_i hid[x,i] * (W[i,j,s] + W[j,i,s])
// GEMM M=768, N=2048, K=64. Tile 64(m) x 64(n), K=64 resident, 256 thr,
// 4x4 micro. Grid (32 n-tiles, 12 m-tiles) = 384 blocks. smem ~33 KB.
// ---------------------------------------------------------------------------
__global__ __launch_bounds__(256)
void prep_kernel(const float* __restrict__ hid, const float* __restrict__ W) {
    __shared__ float sHk[DD][68];     // [k][m], pad 68 keeps 16B alignment
    __shared__ float sW[DD][64];      // [k][n] symmetrized

    const int tid = threadIdx.x;
    const int tx = tid & 15;          // n micro (4 each)
    const int ty = tid >> 4;          // m micro (4 each)
    const int m0 = blockIdx.y * 64;
    const int n0 = blockIdx.x * 64;
    const int j0 = n0 >> 5;           // first j covered by this n-tile (spans 2)

    // hid tile: hid[m0+m][k] -> sHk[k][m]  (64 m x 64 k)
    {
        const int m  = tid & 63;
        const int kq = (tid >> 6) * 16;   // 0,16,32,48
#pragma unroll
        for (int r = 0; r < 4; ++r) {
            float4 v = *(const float4*)(hid + (size_t)(m0 + m) * DD + kq + r * 4);
            sHk[kq + r * 4 + 0][m] = v.x;
            sHk[kq + r * 4 + 1][m] = v.y;
            sHk[kq + r * 4 + 2][m] = v.z;
            sHk[kq + r * 4 + 3][m] = v.w;
        }
    }
    // Wsym tile: sW[k][n] = W[k][n0+n] + W[j0 + n/32][k*32 + n%32]
    {
#pragma unroll
        for (int r = 0; r < 4; ++r) {
            const int idx4 = tid + r * 256;     // float4 index, 0..1023
            const int k  = idx4 >> 4;
            const int n4 = idx4 & 15;           // n = n4*4
            const int j  = n4 >> 3;             // 0 or 1
            const int s  = (n4 * 4) & 31;
            float4 a = *(const float4*)(W + (size_t)k * 2048 + n0 + n4 * 4);
            float4 b = *(const float4*)(W + (size_t)(j0 + j) * 2048 + k * 32 + s);
            *(float4*)(&sW[k][n4 * 4]) =
                make_float4(a.x + b.x, a.y + b.y, a.z + b.z, a.w + b.w);
        }
    }
    __syncthreads();

    float acc[4][4];
#pragma unroll
    for (int i = 0; i < 4; ++i)
#pragma unroll
        for (int j = 0; j < 4; ++j) acc[i][j] = 0.0f;

#pragma unroll 8
    for (int k = 0; k < DD; ++k) {
        float4 a4 = *(const float4*)(&sHk[k][ty * 4]);
        float4 b4 = *(const float4*)(&sW[k][tx * 4]);
        float a[4] = {a4.x, a4.y, a4.z, a4.w};
        float b[4] = {b4.x, b4.y, b4.z, b4.w};
#pragma unroll
        for (int i = 0; i < 4; ++i)
#pragma unroll
            for (int j = 0; j < 4; ++j) acc[i][j] += a[i] * b[j];
    }

#pragma unroll
    for (int i = 0; i < 4; ++i) {
        const int m = m0 + ty * 4 + i;
        *(float4*)(g_A + (size_t)m * 2048 + n0 + tx * 4) =
            make_float4(acc[i][0], acc[i][1], acc[i][2], acc[i][3]);
    }
}

// ---------------------------------------------------------------------------
// Kernel 2: block x handles only y > x (symmetrized pairs).
// 256 threads: tid&127 -> y in tile, tid>>7 -> which half of s (16 each).
// intersym[s] = 2*b[s] + sum_j Asym[x][j][s] * hid[y][j]
// per pose p: acc_p += sum_s intersym[s] * 2^(C2LOG*(d-mu_s)^2)
// ---------------------------------------------------------------------------
__global__ __launch_bounds__(256, 2)
void main_kernel(const float* __restrict__ hid, const float* __restrict__ coords,
                 const float* __restrict__ b_rbf) {
    __shared__ float sA[DD * SS];        // 8 KB  [j][s]
    __shared__ float sH[DD][129];        // 33 KB [j][y]
    __shared__ float sCy[PP][3][128];    // 6 KB
    __shared__ float sb[SS];
    __shared__ float scx[PP * 3];
    __shared__ float sred[8][4];

    const int x   = blockIdx.x;
    const int tid = threadIdx.x;
    const int y_l = tid & 127;
    const int sh  = tid >> 7;            // 0 or 1
    const int s_base = sh * 16;

    // Load Asym_x (2048 floats)
    {
        const float4* gA4 = (const float4*)(g_A + (size_t)x * (DD * SS));
        float4* sA4w = (float4*)sA;
        sA4w[tid]       = gA4[tid];
        sA4w[tid + 256] = gA4[tid + 256];
    }
    if (tid < SS) sb[tid] = b_rbf[tid];
    if (tid < PP * 3) {
        const int p = tid / 3, c = tid - p * 3;
        scx[tid] = coords[(size_t)(p * NN + x) * 3 + c];
    }

    float acc[PP] = {0.f, 0.f, 0.f, 0.f};

    for (int ytile = x & ~127; ytile < NN; ytile += 128) {
        __syncthreads();
        // hid tile transposed: hid[ytile+y][j] -> sH[j][y]
        {
            const int yy = tid >> 4;
            const int j4 = (tid & 15) * 4;
#pragma unroll
            for (int r = 0; r < 8; ++r) {
                const int y = yy + r * 16;
                float4 v = *(const float4*)(hid + (size_t)(ytile + y) * DD + j4);
                sH[j4 + 0][y] = v.x;
                sH[j4 + 1][y] = v.y;
                sH[j4 + 2][y] = v.z;
                sH[j4 + 3][y] = v.w;
            }
        }
        // coords tile
        for (int idx = tid; idx < PP * 128 * 3; idx += 256) {
            const int p   = idx / (128 * 3);
            const int rem = idx - p * (128 * 3);
            const int y   = rem / 3;
            const int c   = rem - y * 3;
            sCy[p][c][y] = coords[(size_t)(p * NN + ytile + y) * 3 + c];
        }
        __syncthreads();

        float inter[16];
#pragma unroll
        for (int s = 0; s < 16; ++s) inter[s] = 2.0f * sb[s_base + s];

        const float4* sA4 = (const float4*)sA;
        const int abase = sh * 4;
#pragma unroll 4
        for (int j = 0; j < DD; ++j) {
            const float h = sH[j][y_l];
            float4 a0 = sA4[j * 8 + abase + 0];
            float4 a1 = sA4[j * 8 + abase + 1];
            float4 a2 = sA4[j * 8 + abase + 2];
            float4 a3 = sA4[j * 8 + abase + 3];
            inter[0]  += a0.x * h; inter[1]  += a0.y * h;
            inter[2]  += a0.z * h; inter[3]  += a0.w * h;
            inter[4]  += a1.x * h; inter[5]  += a1.y * h;
            inter[6]  += a1.z * h; inter[7]  += a1.w * h;
            inter[8]  += a2.x * h; inter[9]  += a2.y * h;
            inter[10] += a2.z * h; inter[11] += a2.w * h;
            inter[12] += a3.x * h; inter[13] += a3.y * h;
            inter[14] += a3.z * h; inter[15] += a3.w * h;
        }

        const int yg = ytile + y_l;
        if (yg > x) {
            const float mu_base = (float)s_base * RBF_STEP;
#pragma unroll
            for (int p = 0; p < PP; ++p) {
                const float dx = scx[p * 3 + 0] - sCy[p][0][y_l];
                const float dy = scx[p * 3 + 1] - sCy[p][1][y_l];
                const float dz = scx[p * 3 + 2] - sCy[p][2][y_l];
                const float d  = sqrtf(dx * dx + dy * dy + dz * dz + 1e-12f);
                float t = d - mu_base;
                float a = 0.0f;
#pragma unroll
                for (int s = 0; s < 16; ++s) {
                    const float ct = t * C2LOG;
                    const float e = ex2f(ct * t);
                    a += inter[s] * e;
                    t -= RBF_STEP;
                }
                acc[p] += a;
            }
        }
    }

    // Deterministic block reduction
#pragma unroll
    for (int p = 0; p < PP; ++p) {
#pragma unroll
        for (int off = 16; off > 0; off >>= 1)
            acc[p] += __shfl_down_sync(0xffffffffu, acc[p], off);
    }
    const int wid = tid >> 5, lane = tid & 31;
    if (lane == 0) {
#pragma unroll
        for (int p = 0; p < PP; ++p) sred[wid][p] = acc[p];
    }
    __syncthreads();
    if (tid < PP) {
        float s = 0.0f;
#pragma unroll
        for (int w = 0; w < 8; ++w) s += sred[w][tid];
        g_partial[x * PP + tid] = s;
    }
}

// ---------------------------------------------------------------------------
// Kernel 3: reduce partials, scale, bias.
// ---------------------------------------------------------------------------
__global__ __launch_bounds__(256)
void finalize_kernel(const float* __restrict__ weight, const float* __restrict__ bias,
                     float* __restrict__ out) {
    __shared__ float red[256][4];
    const int tid = threadIdx.x;
    float a[PP] = {0.f, 0.f, 0.f, 0.f};
    for (int i = tid; i < NN; i += 256) {
#pragma unroll
        for (int p = 0; p < PP; ++p) a[p] += g_partial[i * PP + p];
    }
#pragma unroll
    for (int p = 0; p < PP; ++p) red[tid][p] = a[p];
    for (int off = 128; off > 0; off >>= 1) {
        __syncthreads();
        if (tid < off) {
#pragma unroll
            for (int p = 0; p < PP; ++p) red[tid][p] += red[tid + off][p];
        }
    }
    __syncthreads();
    if (tid < PP) {
        const float scale = 1.0f / (float)((size_t)NN * NN * SS);  // ENERGY_SCALE = 1
        out[tid] = red[0][tid] * scale * weight[0] + bias[0];
    }
}

// ---------------------------------------------------------------------------
extern "C" void kernel_launch(void* const* d_in, const int* in_sizes, int n_in,
                              void* d_out, int out_size) {
    const float* hid    = (const float*)d_in[0];   // [768,64]
    const float* coords = (const float*)d_in[1];   // [4,768,3]
    const float* W_rbf  = (const float*)d_in[2];   // [64,64,32]
    const float* b_rbf  = (const float*)d_in[3];   // [32]
    const float* weight = (const float*)d_in[4];   // [1]
    const float* bias   = (const float*)d_in[5];   // [1]
    float* out = (float*)d_out;                    // [4]

    prep_kernel<<<dim3(32, 12), 256>>>(hid, W_rbf);
    main_kernel<<<NN, 256>>>(hid, coords, b_rbf);
    finalize_kernel<<<1, 256>>>(weight, bias, out);
}

// round 4
// speedup vs baseline: 2.2074x; 1.2560x over previous
#include <cuda_runtime.h>
#include <math.h>

// Problem constants
#define NN 768
#define DD 64
#define SS 32
#define PP 4

// RBF constants: mu = linspace(0,12,32) -> step 12/31 ; sigma = 12/32
#define RBF_STEP    (12.0f / 31.0f)
// exp(-t^2/(2*sigma^2)) = 2^(C2LOG * t^2), C2LOG = -1/(2*sigma^2) * log2(e)
#define C2LOG       (-5.1295823676f)

// Scratch: Asym = hid @ (W + W^T_ij)  -> [x][j][s], 6 MB
__device__ float g_A[NN * DD * SS];
__device__ float g_partial[NN * PP];

__device__ __forceinline__ float ex2f(float x) {
    float r;
    asm("ex2.approx.f32 %0, %1;" : "=f"(r) : "f"(x));
    return r;
}

// ---------------------------------------------------------------------------
// Kernel 1: Asym[x, j*32+s] = sum_i hid[x,i] * (W[i,j,s] + W[j,i,s])
// (unchanged from round 3: 64x64 tiles, K=64 resident, 4x4 micro, 384 blocks)
// ---------------------------------------------------------------------------
__global__ __launch_bounds__(256)
void prep_kernel(const float* __restrict__ hid, const float* __restrict__ W) {
    __shared__ float sHk[DD][68];
    __shared__ float sW[DD][64];

    const int tid = threadIdx.x;
    const int tx = tid & 15;
    const int ty = tid >> 4;
    const int m0 = blockIdx.y * 64;
    const int n0 = blockIdx.x * 64;
    const int j0 = n0 >> 5;

    {
        const int m  = tid & 63;
        const int kq = (tid >> 6) * 16;
#pragma unroll
        for (int r = 0; r < 4; ++r) {
            float4 v = *(const float4*)(hid + (size_t)(m0 + m) * DD + kq + r * 4);
            sHk[kq + r * 4 + 0][m] = v.x;
            sHk[kq + r * 4 + 1][m] = v.y;
            sHk[kq + r * 4 + 2][m] = v.z;
            sHk[kq + r * 4 + 3][m] = v.w;
        }
    }
    {
#pragma unroll
        for (int r = 0; r < 4; ++r) {
            const int idx4 = tid + r * 256;
            const int k  = idx4 >> 4;
            const int n4 = idx4 & 15;
            const int j  = n4 >> 3;
            const int s  = (n4 * 4) & 31;
            float4 a = *(const float4*)(W + (size_t)k * 2048 + n0 + n4 * 4);
            float4 b = *(const float4*)(W + (size_t)(j0 + j) * 2048 + k * 32 + s);
            *(float4*)(&sW[k][n4 * 4]) =
                make_float4(a.x + b.x, a.y + b.y, a.z + b.z, a.w + b.w);
        }
    }
    __syncthreads();

    float acc[4][4];
#pragma unroll
    for (int i = 0; i < 4; ++i)
#pragma unroll
        for (int j = 0; j < 4; ++j) acc[i][j] = 0.0f;

#pragma unroll 8
    for (int k = 0; k < DD; ++k) {
        float4 a4 = *(const float4*)(&sHk[k][ty * 4]);
        float4 b4 = *(const float4*)(&sW[k][tx * 4]);
        float a[4] = {a4.x, a4.y, a4.z, a4.w};
        float b[4] = {b4.x, b4.y, b4.z, b4.w};
#pragma unroll
        for (int i = 0; i < 4; ++i)
#pragma unroll
            for (int j = 0; j < 4; ++j) acc[i][j] += a[i] * b[j];
    }

#pragma unroll
    for (int i = 0; i < 4; ++i) {
        const int m = m0 + ty * 4 + i;
        *(float4*)(g_A + (size_t)m * 2048 + n0 + tx * 4) =
            make_float4(acc[i][0], acc[i][1], acc[i][2], acc[i][3]);
    }
}

// ---------------------------------------------------------------------------
// Kernel 2: block x handles y > x. 256 threads = 32 y-quads (lane) x 8 s-quads
// (warp). Each thread: 4y x 4s micro-tile.
//   per j: 1 LDS.128 h-quad (conflict-free via swizzle) +
//          1 LDS.128 A-quad (warp-uniform broadcast) -> 16 FMA
// Distances precomputed once per tile into sD[4][128].
// ---------------------------------------------------------------------------
__global__ __launch_bounds__(256, 2)
void main_kernel(const float* __restrict__ hid, const float* __restrict__ coords,
                 const float* __restrict__ b_rbf) {
    __shared__ float4 sH4[DD * 32];   // 32 KB: slot (j, q) at j*32 + (q ^ ((j>>2)&7))
    __shared__ float  sA[DD * SS];    // 8 KB   [j][s]
    __shared__ float  sD[PP][128];    // 2 KB
    __shared__ float  sb[SS];
    __shared__ float  scx[PP * 3];
    __shared__ float  sred[8][4];

    const int x   = blockIdx.x;
    const int tid = threadIdx.x;
    const int yq  = tid & 31;         // y-quad (y = 4*yq .. 4*yq+3)
    const int sg  = tid >> 5;         // s-quad (s = 4*sg .. 4*sg+3) == warp id

    // Load Asym_x (2048 floats, coalesced float4)
    {
        const float4* gA4 = (const float4*)(g_A + (size_t)x * (DD * SS));
        float4* sA4w = (float4*)sA;
        sA4w[tid]       = gA4[tid];
        sA4w[tid + 256] = gA4[tid + 256];
    }
    if (tid < SS) sb[tid] = b_rbf[tid];
    if (tid < PP * 3) {
        const int p = tid / 3, c = tid - p * 3;
        scx[tid] = coords[(size_t)(p * NN + x) * 3 + c];
    }

    float acc[PP] = {0.f, 0.f, 0.f, 0.f};
    const float4* sA4 = (const float4*)sA;
    const float mu0 = (float)(4 * (tid >> 5)) * RBF_STEP;

    for (int ytile = x & ~127; ytile < NN; ytile += 128) {
        __syncthreads();
        // --- load hid tile, transposed to quads-of-y, swizzled ---
        {
            const int u = tid & 15;       // j4 = 4u
            const int w = tid >> 4;       // quad base
#pragma unroll
            for (int r = 0; r < 2; ++r) {
                const int q  = w + r * 16;
                const int yb = ytile + q * 4;
                float4 v0 = *(const float4*)(hid + (size_t)(yb + 0) * DD + 4 * u);
                float4 v1 = *(const float4*)(hid + (size_t)(yb + 1) * DD + 4 * u);
                float4 v2 = *(const float4*)(hid + (size_t)(yb + 2) * DD + 4 * u);
                float4 v3 = *(const float4*)(hid + (size_t)(yb + 3) * DD + 4 * u);
                {
                    const int j = 4 * u + 0;
                    sH4[j * 32 + (q ^ ((j >> 2) & 7))] = make_float4(v0.x, v1.x, v2.x, v3.x);
                }
                {
                    const int j = 4 * u + 1;
                    sH4[j * 32 + (q ^ ((j >> 2) & 7))] = make_float4(v0.y, v1.y, v2.y, v3.y);
                }
                {
                    const int j = 4 * u + 2;
                    sH4[j * 32 + (q ^ ((j >> 2) & 7))] = make_float4(v0.z, v1.z, v2.z, v3.z);
                }
                {
                    const int j = 4 * u + 3;
                    sH4[j * 32 + (q ^ ((j >> 2) & 7))] = make_float4(v0.w, v1.w, v2.w, v3.w);
                }
            }
        }
        // --- distances once per (p, y) ---
        for (int idx = tid; idx < PP * 128; idx += 256) {
            const int p = idx >> 7;
            const int y = idx & 127;
            const float* cy = coords + (size_t)(p * NN + ytile + y) * 3;
            const float dx = scx[p * 3 + 0] - cy[0];
            const float dy = scx[p * 3 + 1] - cy[1];
            const float dz = scx[p * 3 + 2] - cy[2];
            sD[p][y] = sqrtf(dx * dx + dy * dy + dz * dz + 1e-12f);
        }
        __syncthreads();

        // --- GEMM: inter[yc][sc] = 2*b + sum_j A[x][j][4sg+sc] * h[y][j] ---
        float i00 = 2.0f * sb[4 * sg + 0], i01 = 2.0f * sb[4 * sg + 1];
        float i02 = 2.0f * sb[4 * sg + 2], i03 = 2.0f * sb[4 * sg + 3];
        float i10 = i00, i11 = i01, i12 = i02, i13 = i03;
        float i20 = i00, i21 = i01, i22 = i02, i23 = i03;
        float i30 = i00, i31 = i01, i32 = i02, i33 = i03;

#pragma unroll 8
        for (int j = 0; j < DD; ++j) {
            const float4 h = sH4[j * 32 + (yq ^ ((j >> 2) & 7))];
            const float4 a = sA4[j * 8 + sg];
            i00 += h.x * a.x; i01 += h.x * a.y; i02 += h.x * a.z; i03 += h.x * a.w;
            i10 += h.y * a.x; i11 += h.y * a.y; i12 += h.y * a.z; i13 += h.y * a.w;
            i20 += h.z * a.x; i21 += h.z * a.y; i22 += h.z * a.z; i23 += h.z * a.w;
            i30 += h.w * a.x; i31 += h.w * a.y; i32 += h.w * a.z; i33 += h.w * a.w;
        }

        // --- epilogue ---
        const int yb = ytile + 4 * yq;
        const bool p0 = (yb + 0) > x;
        const bool p1 = (yb + 1) > x;
        const bool p2 = (yb + 2) > x;
        const bool p3 = (yb + 3) > x;

#pragma unroll
        for (int p = 0; p < PP; ++p) {
            const float4 dq = *(const float4*)(&sD[p][4 * yq]);
            float a = 0.0f;
            if (p0) {
                float t = dq.x - mu0;
                a += i00 * ex2f(C2LOG * t * t); t -= RBF_STEP;
                a += i01 * ex2f(C2LOG * t * t); t -= RBF_STEP;
                a += i02 * ex2f(C2LOG * t * t); t -= RBF_STEP;
                a += i03 * ex2f(C2LOG * t * t);
            }
            if (p1) {
                float t = dq.y - mu0;
                a += i10 * ex2f(C2LOG * t * t); t -= RBF_STEP;
                a += i11 * ex2f(C2LOG * t * t); t -= RBF_STEP;
                a += i12 * ex2f(C2LOG * t * t); t -= RBF_STEP;
                a += i13 * ex2f(C2LOG * t * t);
            }
            if (p2) {
                float t = dq.z - mu0;
                a += i20 * ex2f(C2LOG * t * t); t -= RBF_STEP;
                a += i21 * ex2f(C2LOG * t * t); t -= RBF_STEP;
                a += i22 * ex2f(C2LOG * t * t); t -= RBF_STEP;
                a += i23 * ex2f(C2LOG * t * t);
            }
            if (p3) {
                float t = dq.w - mu0;
                a += i30 * ex2f(C2LOG * t * t); t -= RBF_STEP;
                a += i31 * ex2f(C2LOG * t * t); t -= RBF_STEP;
                a += i32 * ex2f(C2LOG * t * t); t -= RBF_STEP;
                a += i33 * ex2f(C2LOG * t * t);
            }
            acc[p] += a;
        }
    }

    // Deterministic block reduction
#pragma unroll
    for (int p = 0; p < PP; ++p) {
#pragma unroll
        for (int off = 16; off > 0; off >>= 1)
            acc[p] += __shfl_down_sync(0xffffffffu, acc[p], off);
    }
    const int wid = tid >> 5, lane = tid & 31;
    if (lane == 0) {
#pragma unroll
        for (int p = 0; p < PP; ++p) sred[wid][p] = acc[p];
    }
    __syncthreads();
    if (tid < PP) {
        float s = 0.0f;
#pragma unroll
        for (int w = 0; w < 8; ++w) s += sred[w][tid];
        g_partial[x * PP + tid] = s;
    }
}

// ---------------------------------------------------------------------------
// Kernel 3: reduce partials, scale, bias.
// ---------------------------------------------------------------------------
__global__ __launch_bounds__(256)
void finalize_kernel(const float* __restrict__ weight, const float* __restrict__ bias,
                     float* __restrict__ out) {
    __shared__ float red[256][4];
    const int tid = threadIdx.x;
    float a[PP] = {0.f, 0.f, 0.f, 0.f};
    for (int i = tid; i < NN; i += 256) {
#pragma unroll
        for (int p = 0; p < PP; ++p) a[p] += g_partial[i * PP + p];
    }
#pragma unroll
    for (int p = 0; p < PP; ++p) red[tid][p] = a[p];
    for (int off = 128; off > 0; off >>= 1) {
        __syncthreads();
        if (tid < off) {
#pragma unroll
            for (int p = 0; p < PP; ++p) red[tid][p] += red[tid + off][p];
        }
    }
    __syncthreads();
    if (tid < PP) {
        const float scale = 1.0f / (float)((size_t)NN * NN * SS);  // ENERGY_SCALE = 1
        out[tid] = red[0][tid] * scale * weight[0] + bias[0];
    }
}

// ---------------------------------------------------------------------------
extern "C" void kernel_launch(void* const* d_in, const int* in_sizes, int n_in,
                              void* d_out, int out_size) {
    const float* hid    = (const float*)d_in[0];   // [768,64]
    const float* coords = (const float*)d_in[1];   // [4,768,3]
    const float* W_rbf  = (const float*)d_in[2];   // [64,64,32]
    const float* b_rbf  = (const float*)d_in[3];   // [32]
    const float* weight = (const float*)d_in[4];   // [1]
    const float* bias   = (const float*)d_in[5];   // [1]
    float* out = (float*)d_out;                    // [4]

    prep_kernel<<<dim3(32, 12), 256>>>(hid, W_rbf);
    main_kernel<<<NN, 256>>>(hid, coords, b_rbf);
    finalize_kernel<<<1, 256>>>(weight, bias, out);
}

// round 7
// speedup vs baseline: 2.6679x; 1.2086x over previous
#include <cuda_runtime.h>
#include <cuda_bf16.h>
#include <math.h>

#define NN 768
#define DD 64
#define SS 32
#define PP 4

#define RBF_STEP  (12.0f / 31.0f)
#define C2LOG     (-5.1295823676f)   // -1/(2*sigma^2) * log2(e), sigma = 12/32

#define PITCH  72                    // bf16 row pitch (144 B): conflict-free frags
#define NBLK   (6 * NN)              // 2D grid: 6 ytiles x 768 x (some early-exit)

// Scratch (bf16 split) + generous padding against any residual OOB
__device__ __align__(16) __nv_bfloat16 g_Bhi[NN * SS * PITCH + 128];
__device__ __align__(16) __nv_bfloat16 g_Blo[NN * SS * PITCH + 128];
__device__ __align__(16) __nv_bfloat16 g_Hhi[NN * PITCH + 128];
__device__ __align__(16) __nv_bfloat16 g_Hlo[NN * PITCH + 128];
__device__ float g_partial[NBLK * PP + 64];

__device__ __forceinline__ float ex2f(float x) {
    float r; asm("ex2.approx.f32 %0, %1;" : "=f"(r) : "f"(x)); return r;
}

__device__ __forceinline__ void mma_bf16(float& c0, float& c1, float& c2, float& c3,
                                         unsigned a0, unsigned a1, unsigned a2, unsigned a3,
                                         unsigned b0, unsigned b1) {
    asm volatile(
        "mma.sync.aligned.m16n8k16.row.col.f32.bf16.bf16.f32 "
        "{%0,%1,%2,%3}, {%4,%5,%6,%7}, {%8,%9}, {%0,%1,%2,%3};"
        : "+f"(c0), "+f"(c1), "+f"(c2), "+f"(c3)
        : "r"(a0), "r"(a1), "r"(a2), "r"(a3), "r"(b0), "r"(b1));
}

// ---------------------------------------------------------------------------
// Kernel 1: Asym[x][j][s] = sum_i hid[x,i]*(W[i,j,s]+W[j,i,s]); written as
// split-bf16 into g_Bhi/g_Blo with layout [x][s][j] (pitch 72).
// blockIdx.x==0 blocks also convert hid rows -> g_Hhi/g_Hlo.
// ---------------------------------------------------------------------------
__global__ __launch_bounds__(256)
void prep_kernel(const float* __restrict__ hid, const float* __restrict__ W) {
    __shared__ float sHk[DD][36];     // [k][m]
    __shared__ float sW[DD][128];     // [k][n], n = j*32+s

    const int tid = threadIdx.x;
    const int tx = tid & 31;          // s
    const int ty = tid >> 5;          // m micro (4 each)
    const int m0 = blockIdx.y * 32;
    const int n0 = blockIdx.x * 128;
    const int j0 = n0 >> 5;           // 4 j's per block

    {   // hid tile: hid[m0+m][k] -> sHk[k][m]
        const int m  = tid & 31;
        const int k0 = (tid >> 5) * 8;
        float4 a = *(const float4*)(hid + (size_t)(m0 + m) * DD + k0);
        float4 b = *(const float4*)(hid + (size_t)(m0 + m) * DD + k0 + 4);
        sHk[k0 + 0][m] = a.x; sHk[k0 + 1][m] = a.y;
        sHk[k0 + 2][m] = a.z; sHk[k0 + 3][m] = a.w;
        sHk[k0 + 4][m] = b.x; sHk[k0 + 5][m] = b.y;
        sHk[k0 + 6][m] = b.z; sHk[k0 + 7][m] = b.w;
    }
    {   // Wsym tile
#pragma unroll
        for (int r = 0; r < 8; ++r) {
            const int idx4 = tid + r * 256;       // 0..2047
            const int k  = idx4 >> 5;
            const int n4 = idx4 & 31;
            const int j  = n4 >> 3;
            const int s  = (n4 * 4) & 31;
            float4 a = *(const float4*)(W + (size_t)k * 2048 + n0 + n4 * 4);
            float4 b = *(const float4*)(W + (size_t)(j0 + j) * 2048 + k * 32 + s);
            *(float4*)(&sW[k][n4 * 4]) =
                make_float4(a.x + b.x, a.y + b.y, a.z + b.z, a.w + b.w);
        }
    }
    // H conversion (blocks with blockIdx.x==0 cover all 768 rows via blockIdx.y)
    if (blockIdx.x == 0) {
#pragma unroll
        for (int r = 0; r < 8; ++r) {
            const int idx = tid + r * 256;        // 0..2047 = 32 rows x 64 j
            const int m = m0 + (idx >> 6);
            const int j = idx & 63;
            const float v = hid[(size_t)m * DD + j];
            const __nv_bfloat16 h = __float2bfloat16_rn(v);
            g_Hhi[(size_t)m * PITCH + j] = h;
            g_Hlo[(size_t)m * PITCH + j] = __float2bfloat16_rn(v - __bfloat162float(h));
        }
    }
    __syncthreads();

    float acc[4][4];
#pragma unroll
    for (int i = 0; i < 4; ++i)
#pragma unroll
        for (int j = 0; j < 4; ++j) acc[i][j] = 0.0f;

#pragma unroll 8
    for (int k = 0; k < DD; ++k) {
        float4 a4 = *(const float4*)(&sHk[k][ty * 4]);   // warp-uniform broadcast
        float a[4] = {a4.x, a4.y, a4.z, a4.w};
        float b[4] = {sW[k][tx], sW[k][32 + tx], sW[k][64 + tx], sW[k][96 + tx]};
#pragma unroll
        for (int i = 0; i < 4; ++i)
#pragma unroll
            for (int j = 0; j < 4; ++j) acc[i][j] += a[i] * b[j];
    }

#pragma unroll
    for (int i = 0; i < 4; ++i) {
        const int m = m0 + ty * 4 + i;
        const size_t base = (size_t)m * (SS * PITCH) + (size_t)tx * PITCH + j0;
#pragma unroll
        for (int jj = 0; jj < 4; ++jj) {
            const float v = acc[i][jj];
            const __nv_bfloat16 h = __float2bfloat16_rn(v);
            g_Bhi[base + jj] = h;
            g_Blo[base + jj] = __float2bfloat16_rn(v - __bfloat162float(h));
        }
    }
}

// ---------------------------------------------------------------------------
// Kernel 2: grid (6, 768): blockIdx.x = ytile index t, blockIdx.y = x.
// Blocks with t < x>>7 exit early (write zero partials). 128 thr = 4 warps.
// D[128,32] = H[128,64] @ Asym_x[64,32] via mma.sync bf16, 3 split passes,
// then fused RBF epilogue over y > x.
// ---------------------------------------------------------------------------
__global__ __launch_bounds__(128)
void main_kernel(const float* __restrict__ coords, const float* __restrict__ b_rbf) {
    __shared__ __align__(16) __nv_bfloat16 sHhi[128 * PITCH + 64];  // +128B pad
    __shared__ __align__(16) __nv_bfloat16 sHlo[128 * PITCH + 64];
    __shared__ __align__(16) __nv_bfloat16 sBhi[SS * PITCH + 64];
    __shared__ __align__(16) __nv_bfloat16 sBlo[SS * PITCH + 64];
    __shared__ float sD[PP * 128];
    __shared__ float sb[SS];
    __shared__ float scx[PP * 3];
    __shared__ float sred[16];

    const int tid  = threadIdx.x;
    const int wid  = tid >> 5, lane = tid & 31;

    const int t = blockIdx.x;            // 0..5
    const int x = blockIdx.y;            // 0..767
    const int pslot = (x * 6 + t) * PP;

    if (t < (x >> 7)) {                  // uniform across block: no pairs here
        if (tid < PP) g_partial[pslot + tid] = 0.0f;
        return;
    }
    const int ytile = t * 128;

    if (tid < SS) sb[tid] = b_rbf[tid];
    if (tid < PP * 3) {
        const int p = tid / 3, c = tid - p * 3;
        scx[tid] = coords[(size_t)(p * NN + x) * 3 + c];
    }
    __syncthreads();   // scx visible before distance calc

    // --- copy H tiles (1152 uint4 each) ---
    {
        const uint4* gh = (const uint4*)(g_Hhi + (size_t)ytile * PITCH);
        const uint4* gl = (const uint4*)(g_Hlo + (size_t)ytile * PITCH);
        uint4* shh = (uint4*)sHhi;
        uint4* shl = (uint4*)sHlo;
#pragma unroll
        for (int q = 0; q < 9; ++q) {
            shh[tid + q * 128] = gh[tid + q * 128];
            shl[tid + q * 128] = gl[tid + q * 128];
        }
    }
    // --- copy B tiles (288 uint4 each) ---
    {
        const uint4* gh = (const uint4*)(g_Bhi + (size_t)x * (SS * PITCH));
        const uint4* gl = (const uint4*)(g_Blo + (size_t)x * (SS * PITCH));
        uint4* sbh = (uint4*)sBhi;
        uint4* sbl = (uint4*)sBlo;
        for (int idx = tid; idx < 288; idx += 128) {
            sbh[idx] = gh[idx];
            sbl[idx] = gl[idx];
        }
    }
    // --- distances ---
#pragma unroll
    for (int q = 0; q < 4; ++q) {
        const int idx = tid + q * 128;
        const int p = idx >> 7, y = idx & 127;
        const float* cy = coords + (size_t)(p * NN + ytile + y) * 3;
        const float dx = scx[p * 3 + 0] - cy[0];
        const float dy = scx[p * 3 + 1] - cy[1];
        const float dz = scx[p * 3 + 2] - cy[2];
        sD[idx] = sqrtf(dx * dx + dy * dy + dz * dz + 1e-12f);
    }
    __syncthreads();

    // --- MMA: thread covers y = 32w + 16i + lane/4 (+8), s = 8t2 + 2*(lane%4) (+1) ---
    float c[2][4][4];
#pragma unroll
    for (int i = 0; i < 2; ++i)
#pragma unroll
        for (int t2 = 0; t2 < 4; ++t2)
#pragma unroll
            for (int q = 0; q < 4; ++q) c[i][t2][q] = 0.0f;

    const int arow = (lane >> 2);        // 0..7
    const int acol = (lane & 3) * 2;     // 0,2,4,6

#pragma unroll
    for (int pass = 0; pass < 3; ++pass) {
        const __nv_bfloat16* Hp = (pass == 2) ? sHlo : sHhi;
        const __nv_bfloat16* Bp = (pass == 1) ? sBlo : sBhi;
#pragma unroll
        for (int kt = 0; kt < 4; ++kt) {
            const int k0 = kt * 16;
            unsigned a[2][4], bb[4][2];
#pragma unroll
            for (int i = 0; i < 2; ++i) {
                const int yb = 32 * wid + 16 * i + arow;
                const __nv_bfloat16* hp = Hp + (size_t)yb * PITCH + k0 + acol;
                a[i][0] = *(const unsigned*)(hp);
                a[i][1] = *(const unsigned*)(hp + 8 * PITCH);
                a[i][2] = *(const unsigned*)(hp + 8);
                a[i][3] = *(const unsigned*)(hp + 8 * PITCH + 8);
            }
#pragma unroll
            for (int t2 = 0; t2 < 4; ++t2) {
                const int n = t2 * 8 + arow;
                const __nv_bfloat16* bp = Bp + (size_t)n * PITCH + k0 + acol;
                bb[t2][0] = *(const unsigned*)(bp);
                bb[t2][1] = *(const unsigned*)(bp + 8);
            }
#pragma unroll
            for (int i = 0; i < 2; ++i)
#pragma unroll
                for (int t2 = 0; t2 < 4; ++t2)
                    mma_bf16(c[i][t2][0], c[i][t2][1], c[i][t2][2], c[i][t2][3],
                             a[i][0], a[i][1], a[i][2], a[i][3],
                             bb[t2][0], bb[t2][1]);
        }
    }

    // --- epilogue ---
    const int cbase = 2 * (lane & 3);
    float acc[PP] = {0.f, 0.f, 0.f, 0.f};
#pragma unroll
    for (int i = 0; i < 2; ++i) {
#pragma unroll
        for (int half = 0; half < 2; ++half) {
            const int y = 32 * wid + 16 * i + arow + 8 * half;
            if (ytile + y > x) {
#pragma unroll
                for (int p = 0; p < PP; ++p) {
                    const float dd = sD[p * 128 + y];
                    float a = 0.0f;
#pragma unroll
                    for (int t2 = 0; t2 < 4; ++t2) {
#pragma unroll
                        for (int cc = 0; cc < 2; ++cc) {
                            const int s = t2 * 8 + cbase + cc;
                            const float inter = c[i][t2][half * 2 + cc] + 2.0f * sb[s];
                            const float tt = dd - (float)s * RBF_STEP;
                            a += inter * ex2f((C2LOG * tt) * tt);
                        }
                    }
                    acc[p] += a;
                }
            }
        }
    }

    // block reduction (4 warps)
#pragma unroll
    for (int p = 0; p < PP; ++p) {
#pragma unroll
        for (int off = 16; off > 0; off >>= 1)
            acc[p] += __shfl_down_sync(0xffffffffu, acc[p], off);
    }
    if (lane == 0) {
#pragma unroll
        for (int p = 0; p < PP; ++p) sred[wid * 4 + p] = acc[p];
    }
    __syncthreads();
    if (tid < PP) {
        g_partial[pslot + tid] =
            sred[tid] + sred[4 + tid] + sred[8 + tid] + sred[12 + tid];
    }
}

// ---------------------------------------------------------------------------
// Kernel 3: reduce NBLK partials, scale, bias.
// ---------------------------------------------------------------------------
__global__ __launch_bounds__(256)
void finalize_kernel(const float* __restrict__ weight, const float* __restrict__ bias,
                     float* __restrict__ out) {
    __shared__ float red[256][4];
    const int tid = threadIdx.x;
    float a[PP] = {0.f, 0.f, 0.f, 0.f};
    for (int i = tid; i < NBLK; i += 256) {
#pragma unroll
        for (int p = 0; p < PP; ++p) a[p] += g_partial[i * PP + p];
    }
#pragma unroll
    for (int p = 0; p < PP; ++p) red[tid][p] = a[p];
    for (int off = 128; off > 0; off >>= 1) {
        __syncthreads();
        if (tid < off) {
#pragma unroll
            for (int p = 0; p < PP; ++p) red[tid][p] += red[tid + off][p];
        }
    }
    __syncthreads();
    if (tid < PP) {
        const float scale = 1.0f / (float)((size_t)NN * NN * SS);  // ENERGY_SCALE = 1
        out[tid] = red[0][tid] * scale * weight[0] + bias[0];
    }
}

// ---------------------------------------------------------------------------
extern "C" void kernel_launch(void* const* d_in, const int* in_sizes, int n_in,
                              void* d_out, int out_size) {
    const float* hid    = (const float*)d_in[0];   // [768,64]
    const float* coords = (const float*)d_in[1];   // [4,768,3]
    const float* W_rbf  = (const float*)d_in[2];   // [64,64,32]
    const float* b_rbf  = (const float*)d_in[3];   // [32]
    const float* weight = (const float*)d_in[4];   // [1]
    const float* bias   = (const float*)d_in[5];   // [1]
    float* out = (float*)d_out;                    // [4]

    prep_kernel<<<dim3(16, 24), 256>>>(hid, W_rbf);
    main_kernel<<<dim3(6, NN), 128>>>(coords, b_rbf);
    finalize_kernel<<<1, 256>>>(weight, bias, out);
}